// round 14
// baseline (speedup 1.0000x reference)
#include <cuda_runtime.h>
#include <cuda_bf16.h>
#include <math.h>

// Problem constants (fixed shapes from the reference)
constexpr int B_   = 16;
constexpr int T_   = 64;
constexpr int HWC  = 32 * 32 * 64;   // 65536 elements per (b, t) slab
constexpr int PV2  = HWC / 2;        // float2 vectors per slab = 32768
constexpr int NTHR = B_ * PV2;       // total threads = 524288

// Converged configuration (R11-R13): 46 regs -> 5 CTAs/SM naturally, full
// 228KB L1D intact, 64-bit fully-coalesced streams. Measured at the chip's
// mixed-stream HBM ceiling (~6.2 TB/s for 1R:2W) across every structural
// variant tried; traffic floor 768 MB / 6.2 TB/s ~= 121 us kernel time.

__global__ __launch_bounds__(256, 5)
void alif2d_kernel(const float2* __restrict__ x,        // [B, T, HWC/2]
                   const float*  __restrict__ hp_base_step,
                   const float*  __restrict__ hp_base_decay,
                   const float2* __restrict__ step_w_raw, // [HWC/2]
                   const float2* __restrict__ decay_w_raw,
                   const float2* __restrict__ gamma,
                   const float2* __restrict__ beta,
                   float2* __restrict__ out_s,            // [B, T, HWC/2]
                   float2* __restrict__ out_v)            // [B, T, HWC/2]
{
    const int idx = blockIdx.x * blockDim.x + threadIdx.x;   // grid exact

    const int p = idx & (PV2 - 1);    // position within HWC slab (vec units)
    const int b = idx >> 15;          // idx / PV2  (PV2 = 32768 = 2^15)

    const float bs = __ldg(hp_base_step);
    const float bd = __ldg(hp_base_decay);

    const float2 swr = step_w_raw[p];
    const float2 dwr = decay_w_raw[p];
    const float2 g2  = gamma[p];
    const float2 be2 = beta[p];

    float g[2]  = {g2.x, g2.y};
    float be[2] = {be2.x, be2.y};

    float step_eff[2], decay_eff[2];
    {
        float swra[2] = {swr.x, swr.y};
        float dwra[2] = {dwr.x, dwr.y};
#pragma unroll
        for (int i = 0; i < 2; i++) {
            // softplus(x) = log1p(exp(x)); sigmoid(x) = 1/(1+exp(-x))
            float sp  = log1pf(expf(swra[i]));
            float sig = 1.0f / (1.0f + expf(-dwra[i]));
            step_eff[i]  = bs * sp;
            decay_eff[i] = bd + (1.0f - bd) * sig;
        }
    }

    float v[2]   = {0.f, 0.f};
    float vth[2] = {0.f, 0.f};

    const float2* xp = x     + (size_t)b * T_ * PV2 + p;
    float2*       sp = out_s + (size_t)b * T_ * PV2 + p;
    float2*       vp = out_v + (size_t)b * T_ * PV2 + p;

#pragma unroll 4
    for (int t = 0; t < T_; t++) {
        const float2 xv = __ldg(xp + (size_t)t * PV2);
        float xa[2] = {xv.x, xv.y};

        float s_out[2], v_out[2];
#pragma unroll
        for (int i = 0; i < 2; i++) {
            // v = v*0.8 + (x*gamma + beta)
            float vi = fmaf(v[i], 0.8f, fmaf(xa[i], g[i], be[i]));
            float vth_eff = 0.5f + vth[i];
            float s = (vi - vth_eff > 0.0f) ? 1.0f : 0.0f;
            v_out[i] = vi;            // voltages output is pre-reset v
            s_out[i] = s;
            v[i]   = vi - vth_eff * s;
            vth[i] = fmaf(vth[i], decay_eff[i], s * step_eff[i]);
        }

        sp[(size_t)t * PV2] = make_float2(s_out[0], s_out[1]);
        vp[(size_t)t * PV2] = make_float2(v_out[0], v_out[1]);
    }
}

extern "C" void kernel_launch(void* const* d_in, const int* in_sizes, int n_in,
                              void* d_out, int out_size)
{
    // metadata order: x, hp_alpha, hp_base_step, hp_base_decay,
    //                 step_w_raw, decay_w_raw, gamma, beta
    const float2* x    = (const float2*)d_in[0];
    // d_in[1] = hp_alpha (unused in forward pass)
    const float*  hbs  = (const float*)d_in[2];
    const float*  hbd  = (const float*)d_in[3];
    const float2* swr  = (const float2*)d_in[4];
    const float2* dwr  = (const float2*)d_in[5];
    const float2* gam  = (const float2*)d_in[6];
    const float2* bet  = (const float2*)d_in[7];

    const size_t n_per = (size_t)B_ * T_ * HWC;   // 67,108,864 elements
    float2* out_s = (float2*)d_out;
    float2* out_v = (float2*)((float*)d_out + n_per);

    const int threads = 256;
    const int blocks  = NTHR / threads;   // 2048, exact
    alif2d_kernel<<<blocks, threads>>>(x, hbs, hbd, swr, dwr, gam, bet,
                                       out_s, out_v);
}

// round 15
// speedup vs baseline: 1.0073x; 1.0073x over previous
#include <cuda_runtime.h>
#include <cuda_bf16.h>
#include <math.h>

// Problem constants (fixed shapes from the reference)
constexpr int B_   = 16;
constexpr int T_   = 64;
constexpr int HWC  = 32 * 32 * 64;   // 65536 elements per (b, t) slab
constexpr int PV2  = HWC / 2;        // float2 vectors per slab = 32768
constexpr int NTHR = B_ * PV2;       // total threads = 524288

// Converged configuration (R11-R14): 46 regs -> 5 CTAs/SM naturally, full
// 228KB L1D intact, 64-bit fully-coalesced streams. Measured at the chip's
// mixed-stream HBM ceiling (~6.2-6.3 TB/s for 1R:2W) across every structural
// variant tried; traffic floor 768 MB / 6.25 TB/s ~= 120 us kernel time.

__global__ __launch_bounds__(256, 5)
void alif2d_kernel(const float2* __restrict__ x,        // [B, T, HWC/2]
                   const float*  __restrict__ hp_base_step,
                   const float*  __restrict__ hp_base_decay,
                   const float2* __restrict__ step_w_raw, // [HWC/2]
                   const float2* __restrict__ decay_w_raw,
                   const float2* __restrict__ gamma,
                   const float2* __restrict__ beta,
                   float2* __restrict__ out_s,            // [B, T, HWC/2]
                   float2* __restrict__ out_v)            // [B, T, HWC/2]
{
    const int idx = blockIdx.x * blockDim.x + threadIdx.x;   // grid exact

    const int p = idx & (PV2 - 1);    // position within HWC slab (vec units)
    const int b = idx >> 15;          // idx / PV2  (PV2 = 32768 = 2^15)

    const float bs = __ldg(hp_base_step);
    const float bd = __ldg(hp_base_decay);

    const float2 swr = step_w_raw[p];
    const float2 dwr = decay_w_raw[p];
    const float2 g2  = gamma[p];
    const float2 be2 = beta[p];

    float g[2]  = {g2.x, g2.y};
    float be[2] = {be2.x, be2.y};

    float step_eff[2], decay_eff[2];
    {
        float swra[2] = {swr.x, swr.y};
        float dwra[2] = {dwr.x, dwr.y};
#pragma unroll
        for (int i = 0; i < 2; i++) {
            // softplus(x) = log1p(exp(x)); sigmoid(x) = 1/(1+exp(-x))
            float sp  = log1pf(expf(swra[i]));
            float sig = 1.0f / (1.0f + expf(-dwra[i]));
            step_eff[i]  = bs * sp;
            decay_eff[i] = bd + (1.0f - bd) * sig;
        }
    }

    float v[2]   = {0.f, 0.f};
    float vth[2] = {0.f, 0.f};

    const float2* xp = x     + (size_t)b * T_ * PV2 + p;
    float2*       sp = out_s + (size_t)b * T_ * PV2 + p;
    float2*       vp = out_v + (size_t)b * T_ * PV2 + p;

#pragma unroll 4
    for (int t = 0; t < T_; t++) {
        const float2 xv = __ldg(xp + (size_t)t * PV2);
        float xa[2] = {xv.x, xv.y};

        float s_out[2], v_out[2];
#pragma unroll
        for (int i = 0; i < 2; i++) {
            // v = v*0.8 + (x*gamma + beta)
            float vi = fmaf(v[i], 0.8f, fmaf(xa[i], g[i], be[i]));
            float vth_eff = 0.5f + vth[i];
            float s = (vi - vth_eff > 0.0f) ? 1.0f : 0.0f;
            v_out[i] = vi;            // voltages output is pre-reset v
            s_out[i] = s;
            v[i]   = vi - vth_eff * s;
            vth[i] = fmaf(vth[i], decay_eff[i], s * step_eff[i]);
        }

        sp[(size_t)t * PV2] = make_float2(s_out[0], s_out[1]);
        vp[(size_t)t * PV2] = make_float2(v_out[0], v_out[1]);
    }
}

extern "C" void kernel_launch(void* const* d_in, const int* in_sizes, int n_in,
                              void* d_out, int out_size)
{
    // metadata order: x, hp_alpha, hp_base_step, hp_base_decay,
    //                 step_w_raw, decay_w_raw, gamma, beta
    const float2* x    = (const float2*)d_in[0];
    // d_in[1] = hp_alpha (unused in forward pass)
    const float*  hbs  = (const float*)d_in[2];
    const float*  hbd  = (const float*)d_in[3];
    const float2* swr  = (const float2*)d_in[4];
    const float2* dwr  = (const float2*)d_in[5];
    const float2* gam  = (const float2*)d_in[6];
    const float2* bet  = (const float2*)d_in[7];

    const size_t n_per = (size_t)B_ * T_ * HWC;   // 67,108,864 elements
    float2* out_s = (float2*)d_out;
    float2* out_v = (float2*)((float*)d_out + n_per);

    const int threads = 256;
    const int blocks  = NTHR / threads;   // 2048, exact
    alif2d_kernel<<<blocks, threads>>>(x, hbs, hbd, swr, dwr, gam, bet,
                                       out_s, out_v);
}

// round 16
// speedup vs baseline: 1.0123x; 1.0050x over previous
#include <cuda_runtime.h>
#include <cuda_bf16.h>
#include <math.h>

// Problem constants (fixed shapes from the reference)
constexpr int B_   = 16;
constexpr int T_   = 64;
constexpr int HWC  = 32 * 32 * 64;   // 65536 elements per (b, t) slab
constexpr int PV2  = HWC / 2;        // float2 vectors per slab = 32768
constexpr int NTHR = B_ * PV2;       // total threads = 524288

// FINAL converged configuration (R11-R15): 46 regs -> 5 CTAs/SM naturally,
// full 228KB L1D intact, 64-bit fully-coalesced streams. Measured at the
// chip's mixed-stream HBM ceiling (~6.2-6.3 TB/s for 1R:2W) across every
// structural variant tried (prefetch, cache hints, burst shaping, occupancy
// 34-57%, vec width 64/128b, batch pairing). Traffic floor 768 MB / 6.25 TB/s
// ~= 120 us kernel time — this kernel is at its roofline.

__global__ __launch_bounds__(256, 5)
void alif2d_kernel(const float2* __restrict__ x,        // [B, T, HWC/2]
                   const float*  __restrict__ hp_base_step,
                   const float*  __restrict__ hp_base_decay,
                   const float2* __restrict__ step_w_raw, // [HWC/2]
                   const float2* __restrict__ decay_w_raw,
                   const float2* __restrict__ gamma,
                   const float2* __restrict__ beta,
                   float2* __restrict__ out_s,            // [B, T, HWC/2]
                   float2* __restrict__ out_v)            // [B, T, HWC/2]
{
    const int idx = blockIdx.x * blockDim.x + threadIdx.x;   // grid exact

    const int p = idx & (PV2 - 1);    // position within HWC slab (vec units)
    const int b = idx >> 15;          // idx / PV2  (PV2 = 32768 = 2^15)

    const float bs = __ldg(hp_base_step);
    const float bd = __ldg(hp_base_decay);

    const float2 swr = step_w_raw[p];
    const float2 dwr = decay_w_raw[p];
    const float2 g2  = gamma[p];
    const float2 be2 = beta[p];

    float g[2]  = {g2.x, g2.y};
    float be[2] = {be2.x, be2.y};

    float step_eff[2], decay_eff[2];
    {
        float swra[2] = {swr.x, swr.y};
        float dwra[2] = {dwr.x, dwr.y};
#pragma unroll
        for (int i = 0; i < 2; i++) {
            // softplus(x) = log1p(exp(x)); sigmoid(x) = 1/(1+exp(-x))
            float sp  = log1pf(expf(swra[i]));
            float sig = 1.0f / (1.0f + expf(-dwra[i]));
            step_eff[i]  = bs * sp;
            decay_eff[i] = bd + (1.0f - bd) * sig;
        }
    }

    float v[2]   = {0.f, 0.f};
    float vth[2] = {0.f, 0.f};

    const float2* xp = x     + (size_t)b * T_ * PV2 + p;
    float2*       sp = out_s + (size_t)b * T_ * PV2 + p;
    float2*       vp = out_v + (size_t)b * T_ * PV2 + p;

#pragma unroll 4
    for (int t = 0; t < T_; t++) {
        const float2 xv = __ldg(xp + (size_t)t * PV2);
        float xa[2] = {xv.x, xv.y};

        float s_out[2], v_out[2];
#pragma unroll
        for (int i = 0; i < 2; i++) {
            // v = v*0.8 + (x*gamma + beta)
            float vi = fmaf(v[i], 0.8f, fmaf(xa[i], g[i], be[i]));
            float vth_eff = 0.5f + vth[i];
            float s = (vi - vth_eff > 0.0f) ? 1.0f : 0.0f;
            v_out[i] = vi;            // voltages output is pre-reset v
            s_out[i] = s;
            v[i]   = vi - vth_eff * s;
            vth[i] = fmaf(vth[i], decay_eff[i], s * step_eff[i]);
        }

        sp[(size_t)t * PV2] = make_float2(s_out[0], s_out[1]);
        vp[(size_t)t * PV2] = make_float2(v_out[0], v_out[1]);
    }
}

extern "C" void kernel_launch(void* const* d_in, const int* in_sizes, int n_in,
                              void* d_out, int out_size)
{
    // metadata order: x, hp_alpha, hp_base_step, hp_base_decay,
    //                 step_w_raw, decay_w_raw, gamma, beta
    const float2* x    = (const float2*)d_in[0];
    // d_in[1] = hp_alpha (unused in forward pass)
    const float*  hbs  = (const float*)d_in[2];
    const float*  hbd  = (const float*)d_in[3];
    const float2* swr  = (const float2*)d_in[4];
    const float2* dwr  = (const float2*)d_in[5];
    const float2* gam  = (const float2*)d_in[6];
    const float2* bet  = (const float2*)d_in[7];

    const size_t n_per = (size_t)B_ * T_ * HWC;   // 67,108,864 elements
    float2* out_s = (float2*)d_out;
    float2* out_v = (float2*)((float*)d_out + n_per);

    const int threads = 256;
    const int blocks  = NTHR / threads;   // 2048, exact
    alif2d_kernel<<<blocks, threads>>>(x, hbs, hbd, swr, dwr, gam, bet,
                                       out_s, out_v);
}